// round 1
// baseline (speedup 1.0000x reference)
#include <cuda_runtime.h>
#include <math.h>

#define B_   2
#define L_   1408
#define D_   512
#define H_   8
#define DH_  64
#define BH_  16
#define DFF_ 2048
#define BL_  (B_*L_)
#define KSEL_ 704

// ---------------- scratch (device globals; no allocation allowed) ----------------
__device__ float g_xn[BL_*D_];
__device__ float g_q[BH_*L_*DH_];
__device__ float g_k[BH_*L_*DH_];
__device__ float g_adj[(size_t)BH_*L_*L_];     // 126.9 MB
__device__ float g_gates[BH_*L_*3];
__device__ float g_xp[BL_*D_];
__device__ float g_gout[BL_*D_];
__device__ float g_x1[BL_*D_];
__device__ float g_xn2[BL_*D_];
__device__ float g_ffh[(size_t)BL_*DFF_];
__device__ float g_spz[L_*3];
__device__ float g_ent[1];

// ---------------- helpers ----------------
__device__ __forceinline__ float blk_sum(float v, float* s){
    int lane = threadIdx.x & 31, w = threadIdx.x >> 5;
    #pragma unroll
    for(int o=16;o;o>>=1) v += __shfl_down_sync(0xffffffffu, v, o);
    if(lane==0) s[w]=v;
    __syncthreads();
    int nw = blockDim.x >> 5;
    v = (threadIdx.x < nw) ? s[threadIdx.x] : 0.f;
    if(w==0){
        #pragma unroll
        for(int o=16;o;o>>=1) v += __shfl_down_sync(0xffffffffu, v, o);
        if(lane==0) s[0]=v;
    }
    __syncthreads();
    float r = s[0];
    __syncthreads();
    return r;
}

__device__ __forceinline__ float blk_max(float v, float* s){
    int lane = threadIdx.x & 31, w = threadIdx.x >> 5;
    #pragma unroll
    for(int o=16;o;o>>=1) v = fmaxf(v, __shfl_down_sync(0xffffffffu, v, o));
    if(lane==0) s[w]=v;
    __syncthreads();
    int nw = blockDim.x >> 5;
    v = (threadIdx.x < nw) ? s[threadIdx.x] : -INFINITY;
    if(w==0){
        #pragma unroll
        for(int o=16;o;o>>=1) v = fmaxf(v, __shfl_down_sync(0xffffffffu, v, o));
        if(lane==0) s[0]=v;
    }
    __syncthreads();
    float r = s[0];
    __syncthreads();
    return r;
}

__device__ __forceinline__ float geluf(float x){
    return 0.5f * x * (1.0f + erff(x * 0.7071067811865475f));
}

__device__ __forceinline__ unsigned tokey(float f){
    unsigned u = __float_as_uint(f);
    return (u & 0x80000000u) ? ~u : (u | 0x80000000u);
}

// ---------------- kernels ----------------
__global__ void zero_kernel(){
    int i = blockIdx.x*blockDim.x + threadIdx.x;
    if(i < L_*3) g_spz[i] = 0.f;
    if(i == 0)   g_ent[0] = 0.f;
}

__global__ void ln1_kernel(const float* __restrict__ x, const float* __restrict__ g,
                           const float* __restrict__ bta){
    __shared__ float s[32];
    int row = blockIdx.x;
    int t = threadIdx.x;
    const float* xr = x + (size_t)row*D_;
    float v0 = xr[t], v1 = xr[t+256];
    float mean = blk_sum(v0+v1, s) * (1.f/D_);
    float d0 = v0-mean, d1 = v1-mean;
    float var = blk_sum(d0*d0 + d1*d1, s) * (1.f/D_);
    float inv = rsqrtf(var + 1e-5f);
    float* o = g_xn + (size_t)row*D_;
    o[t]     = d0*inv*g[t]     + bta[t];
    o[t+256] = d1*inv*g[t+256] + bta[t+256];
}

__global__ void qk_kernel(const float* __restrict__ w1, const float* __restrict__ b1,
                          const float* __restrict__ w2, const float* __restrict__ b2){
    __shared__ float xr[512];
    __shared__ float W1[4096];
    __shared__ float W2[4096];
    int row = blockIdx.x;            // b*L + l
    int t = threadIdx.x;             // 512
    xr[t] = g_xn[(size_t)row*D_ + t];
    for(int i=t;i<4096;i+=512){ W1[i]=w1[i]; W2[i]=w2[i]; }
    __syncthreads();
    int h = t >> 6, j = t & 63;
    const float* xv = xr + h*64;
    float a1 = b1[j], a2 = b2[j];
    #pragma unroll
    for(int d=0; d<64; d++){
        float v = xv[d];
        a1 += v * W1[d*64+j];
        a2 += v * W2[d*64+j];
    }
    int b = row / L_, l = row % L_;
    size_t o = (((size_t)b*H_ + h)*L_ + l)*64 + j;
    g_q[o] = a1; g_k[o] = a2;
}

__global__ void adj_kernel(){
    __shared__ float Qs[64][65];
    __shared__ float Ks[64][65];
    int bh = blockIdx.z;
    size_t qbase = ((size_t)bh*L_ + blockIdx.y*64)*64;
    size_t kbase = ((size_t)bh*L_ + blockIdx.x*64)*64;
    int t = threadIdx.x;
    for(int i=t;i<4096;i+=256){
        int m = i>>6, kk = i&63;
        Qs[kk][m] = g_q[qbase + (size_t)m*64 + kk];
        Ks[kk][m] = g_k[kbase + (size_t)m*64 + kk];
    }
    __syncthreads();
    int tx = t & 15, ty = t >> 4;
    float acc[4][4] = {};
    #pragma unroll 8
    for(int kk=0; kk<64; kk++){
        float a[4], bv[4];
        #pragma unroll
        for(int i=0;i<4;i++){ a[i]=Qs[kk][ty*4+i]; bv[i]=Ks[kk][tx*4+i]; }
        #pragma unroll
        for(int i=0;i<4;i++)
            #pragma unroll
            for(int j=0;j<4;j++) acc[i][j] += a[i]*bv[j];
    }
    size_t obase = ((size_t)bh*L_ + blockIdx.y*64)*(size_t)L_ + blockIdx.x*64;
    #pragma unroll
    for(int i=0;i<4;i++){
        int r = ty*4+i;
        #pragma unroll
        for(int j=0;j<4;j++){
            g_adj[obase + (size_t)r*L_ + tx*4+j] = geluf(acc[i][j]);
        }
    }
}

// fused: top-k sparsify (exact, jax tie-break) + MoE gating + loss stats
__global__ void topk_gate_kernel(const float* __restrict__ w_gate){
    __shared__ float srow[L_];
    __shared__ unsigned hist[256];
    __shared__ float rs[32];
    __shared__ unsigned sel[3];   // bin, count-below, bin-count
    int row = blockIdx.x;         // bh*L + l
    int l = row % L_;
    int t = threadIdx.x;          // 256
    float* grow = g_adj + (size_t)row*L_;
    for(int i=t;i<L_;i+=256) srow[i] = grow[i];
    __syncthreads();

    // radix-select the KSEL_-th smallest key (1-indexed)
    unsigned prefix = 0, rank = KSEL_, ceq = 0;
    for(int p=3; p>=0; p--){
        hist[t] = 0;
        __syncthreads();
        unsigned shift = p*8;
        unsigned pm = (p==3) ? 0u : (0xFFFFFFFFu << (shift+8));
        for(int i=t;i<L_;i+=256){
            unsigned key = tokey(srow[i]);
            if((key & pm) == prefix) atomicAdd(&hist[(key>>shift)&255u], 1u);
        }
        __syncthreads();
        if(t==0){
            unsigned c = 0;
            for(unsigned bn=0; bn<256; bn++){
                unsigned hc = hist[bn];
                if(c + hc >= rank){ sel[0]=bn; sel[1]=c; sel[2]=hc; break; }
                c += hc;
            }
        }
        __syncthreads();
        prefix |= sel[0] << shift;
        rank   -= sel[1];
        ceq     = sel[2];
        __syncthreads();
    }
    unsigned KT = prefix;
    unsigned rzero = rank;    // #(==KT) entries to zero, 1..ceq; ties -> lowest index first

    for(int i=t;i<L_;i+=256){
        unsigned key = tokey(srow[i]);
        if(key < KT) srow[i] = 0.f;
        else if(key == KT){
            if(rzero >= ceq) srow[i] = 0.f;
            else{
                unsigned r = 0;
                for(int j=0;j<i;j++) if(tokey(grow[j]) == KT) r++;  // grow still unmodified
                if(r < rzero) srow[i] = 0.f;
            }
        }
    }
    __syncthreads();

    // write back masked row + gate dot products
    float z0=0.f, z1=0.f, z2=0.f;
    for(int i=t;i<L_;i+=256){
        float v = srow[i];
        grow[i] = v;
        z0 += v * w_gate[i*3+0];
        z1 += v * w_gate[i*3+1];
        z2 += v * w_gate[i*3+2];
    }
    z0 = blk_sum(z0, rs); z1 = blk_sum(z1, rs); z2 = blk_sum(z2, rs);

    if(t==0){
        float mx = fmaxf(z0, fmaxf(z1, z2));
        float e0 = expf(z0-mx), e1 = expf(z1-mx), e2 = expf(z2-mx);
        float s = e0+e1+e2;
        float p[3] = { e0/s, e1/s, e2/s };
        atomicAdd(g_ent, p[0]*logf(p[0]+1e-10f) + p[1]*logf(p[1]+1e-10f) + p[2]*logf(p[2]+1e-10f));
        // stable descending sort of 3 (ties -> lower index first)
        int o0=0, o1=1, o2=2;
        if(p[o1] > p[o0]){ int tt=o0; o0=o1; o1=tt; }
        if(p[o2] > p[o1]){ int tt=o1; o1=o2; o2=tt; }
        if(p[o1] > p[o0]){ int tt=o0; o0=o1; o1=tt; }
        float sp0=p[o0], sp1=p[o1], sp2=p[o2];
        float c0=sp0, c1=sp0+sp1, c2=sp0+sp1+sp2;
        bool m0 = c0 > 0.5f, m1 = c1 > 0.5f, m2 = c2 > 0.5f;
        int j0 = m0 ? 0 : (m1 ? 1 : 2);          // first crossing
        bool k0 = (!m0) || (j0==0);
        bool k1 = (!m1) || (j0==1);
        bool k2 = (!m2) || (j0==2);
        float gv[3];
        gv[o0] = k0 ? 1.f : 0.f;
        gv[o1] = k1 ? 1.f : 0.f;
        gv[o2] = k2 ? 1.f : 0.f;
        g_gates[row*3+0] = gv[0];
        g_gates[row*3+1] = gv[1];
        g_gates[row*3+2] = gv[2];
        if(k0) atomicAdd(&g_spz[l*3+0], sp0);
        if(k1) atomicAdd(&g_spz[l*3+1], sp1);
        if(k2) atomicAdd(&g_spz[l*3+2], sp2);
    }
}

// final mask mix + row softmax, in place
__global__ void finalize_kernel(const float* __restrict__ masks){
    __shared__ float v[L_];
    __shared__ float rs[32];
    int row = blockIdx.x;
    int l = row % L_;
    int t = threadIdx.x;  // 256
    float gv0 = g_gates[row*3+0], gv1 = g_gates[row*3+1], gv2 = g_gates[row*3+2];
    const float* m0 = masks + ((size_t)l*3 + 0)*L_;
    const float* m1 = masks + ((size_t)l*3 + 1)*L_;
    const float* m2 = masks + ((size_t)l*3 + 2)*L_;
    float* arow = g_adj + (size_t)row*L_;
    float mx = -INFINITY;
    for(int i=t;i<L_;i+=256){
        float fm = (i==l) ? 1.f : 0.f;
        if(gv0 != 0.f) fm += m0[i];
        if(gv1 != 0.f) fm += m1[i];
        if(gv2 != 0.f) fm += m2[i];
        float val = arow[i] * fm;
        v[i] = val;
        mx = fmaxf(mx, val);
    }
    mx = blk_max(mx, rs);
    float s = 0.f;
    for(int i=t;i<L_;i+=256){
        float e = expf(v[i] - mx);
        v[i] = e;
        s += e;
    }
    s = blk_sum(s, rs);
    float inv = 1.f / s;
    for(int i=t;i<L_;i+=256) arow[i] = v[i] * inv;
}

// out[b,i,h*64+d] = sum_j adj[bh,i,j] * xp[b,j,h*64+d]
__global__ void gconv_kernel(){
    __shared__ float As[64][65];
    __shared__ float Bs[64][65];
    int bh = blockIdx.y;
    int b = bh / H_, h = bh % H_;
    int by = blockIdx.x;
    int t = threadIdx.x;
    int tx = t & 15, ty = t >> 4;
    float acc[4][4] = {};
    for(int kt=0; kt<22; kt++){
        for(int i=t;i<4096;i+=256){
            int m = i>>6, kk = i&63;
            As[kk][m] = g_adj[((size_t)bh*L_ + by*64+m)*(size_t)L_ + kt*64+kk];
        }
        for(int i=t;i<4096;i+=256){
            int kk = i>>6, n = i&63;
            Bs[kk][n] = g_xp[((size_t)b*L_ + kt*64+kk)*D_ + h*64 + n];
        }
        __syncthreads();
        #pragma unroll 8
        for(int kk=0; kk<64; kk++){
            float a[4], bv[4];
            #pragma unroll
            for(int i=0;i<4;i++){ a[i]=As[kk][ty*4+i]; bv[i]=Bs[kk][tx*4+i]; }
            #pragma unroll
            for(int i=0;i<4;i++)
                #pragma unroll
                for(int j=0;j<4;j++) acc[i][j] += a[i]*bv[j];
        }
        __syncthreads();
    }
    #pragma unroll
    for(int i=0;i<4;i++){
        int r = by*64 + ty*4 + i;
        #pragma unroll
        for(int j=0;j<4;j++){
            g_gout[((size_t)b*L_ + r)*D_ + h*64 + tx*4+j] = acc[i][j];
        }
    }
}

__global__ void res_ln2_kernel(const float* __restrict__ x, const float* __restrict__ g,
                               const float* __restrict__ bta){
    __shared__ float s[32];
    int row = blockIdx.x;
    int t = threadIdx.x;
    const float* xr = x + (size_t)row*D_;
    const float* gr = g_gout + (size_t)row*D_;
    float a0 = xr[t]     + gr[t];
    float a1 = xr[t+256] + gr[t+256];
    float mean = blk_sum(a0+a1, s) * (1.f/D_);
    float d0 = a0-mean, d1 = a1-mean;
    float var = blk_sum(d0*d0 + d1*d1, s) * (1.f/D_);
    float inv = rsqrtf(var + 1e-5f);
    float* x1r  = g_x1  + (size_t)row*D_;
    float* xn2r = g_xn2 + (size_t)row*D_;
    x1r[t]      = a0;
    x1r[t+256]  = a1;
    xn2r[t]     = d0*inv*g[t]     + bta[t];
    xn2r[t+256] = d1*inv*g[t+256] + bta[t+256];
}

// generic fp32 GEMM: C = act(A@W + bias) (+ res), 64x64 tiles, BK=32
template<int ACT, int RES>
__global__ void gemm_kernel(const float* __restrict__ A, const float* __restrict__ W,
                            const float* __restrict__ bias, const float* __restrict__ res,
                            float* __restrict__ C, int M, int K, int N){
    __shared__ float As[32][65];
    __shared__ float Ws[32][65];
    int n0 = blockIdx.x*64, m0 = blockIdx.y*64;
    int t = threadIdx.x, tx = t & 15, ty = t >> 4;
    float acc[4][4] = {};
    for(int k0=0; k0<K; k0+=32){
        for(int i=t;i<2048;i+=256){
            int m = i>>5, kk = i&31;
            As[kk][m] = A[(size_t)(m0+m)*K + k0+kk];
        }
        for(int i=t;i<2048;i+=256){
            int kk = i>>6, n = i&63;
            Ws[kk][n] = W[(size_t)(k0+kk)*N + n0+n];
        }
        __syncthreads();
        #pragma unroll 8
        for(int kk=0; kk<32; kk++){
            float a[4], bv[4];
            #pragma unroll
            for(int i=0;i<4;i++){ a[i]=As[kk][ty*4+i]; bv[i]=Ws[kk][tx*4+i]; }
            #pragma unroll
            for(int i=0;i<4;i++)
                #pragma unroll
                for(int j=0;j<4;j++) acc[i][j] += a[i]*bv[j];
        }
        __syncthreads();
    }
    #pragma unroll
    for(int i=0;i<4;i++){
        int m = m0 + ty*4 + i;
        #pragma unroll
        for(int j=0;j<4;j++){
            int n = n0 + tx*4 + j;
            float v = acc[i][j] + bias[n];
            if(ACT == 1) v = geluf(v);
            if(RES) v += res[(size_t)m*N + n];
            C[(size_t)m*N + n] = v;
        }
    }
}

__global__ void loss_kernel(const float* __restrict__ spz, const float* __restrict__ ent,
                            float* __restrict__ out){
    __shared__ float rs[32];
    float s = 0.f, sq = 0.f;
    for(int i=threadIdx.x; i<L_*3; i+=256){
        float v = spz[i];
        s += v; sq += v*v;
    }
    s  = blk_sum(s, rs);
    sq = blk_sum(sq, rs);
    if(threadIdx.x == 0){
        const float n = (float)(L_*3);
        float mean = s / n;
        float var = (sq - n*mean*mean) / (n - 1.f);
        float loss_imp = var / (mean*mean + 1e-10f);
        float loss_dyn = -ent[0] / 48.f;   // BH*3
        out[0] = loss_imp + 0.1f*loss_dyn;
    }
}

// ---------------- launch ----------------
extern "C" void kernel_launch(void* const* d_in, const int* in_sizes, int n_in,
                              void* d_out, int out_size){
    const float* x      = (const float*)d_in[0];
    const float* masks  = (const float*)d_in[1];
    const float* ln1_g  = (const float*)d_in[2];
    const float* ln1_b  = (const float*)d_in[3];
    const float* w_p1   = (const float*)d_in[4];
    const float* b_p1   = (const float*)d_in[5];
    const float* w_p2   = (const float*)d_in[6];
    const float* b_p2   = (const float*)d_in[7];
    const float* w_gate = (const float*)d_in[8];
    const float* w_gcn  = (const float*)d_in[9];
    const float* b_gcn  = (const float*)d_in[10];
    const float* ln2_g  = (const float*)d_in[11];
    const float* ln2_b  = (const float*)d_in[12];
    const float* w_f1   = (const float*)d_in[13];
    const float* b_f1   = (const float*)d_in[14];
    const float* w_f2   = (const float*)d_in[15];
    const float* b_f2   = (const float*)d_in[16];
    float* out = (float*)d_out;

    void *p_xn, *p_xp, *p_x1, *p_xn2, *p_ffh, *p_spz, *p_ent;
    cudaGetSymbolAddress(&p_xn,  g_xn);
    cudaGetSymbolAddress(&p_xp,  g_xp);
    cudaGetSymbolAddress(&p_x1,  g_x1);
    cudaGetSymbolAddress(&p_xn2, g_xn2);
    cudaGetSymbolAddress(&p_ffh, g_ffh);
    cudaGetSymbolAddress(&p_spz, g_spz);
    cudaGetSymbolAddress(&p_ent, g_ent);

    zero_kernel<<<17, 256>>>();
    ln1_kernel<<<BL_, 256>>>(x, ln1_g, ln1_b);
    qk_kernel<<<BL_, 512>>>(w_p1, b_p1, w_p2, b_p2);
    {
        dim3 g(L_/64, L_/64, BH_);
        adj_kernel<<<g, 256>>>();
    }
    topk_gate_kernel<<<BH_*L_, 256>>>(w_gate);
    finalize_kernel<<<BH_*L_, 256>>>(masks);
    gemm_kernel<0,0><<<dim3(D_/64, BL_/64), 256>>>((const float*)p_xn, w_gcn, b_gcn,
                                                   nullptr, (float*)p_xp, BL_, D_, D_);
    gconv_kernel<<<dim3(L_/64, BH_), 256>>>();
    res_ln2_kernel<<<BL_, 256>>>(x, ln2_g, ln2_b);
    gemm_kernel<1,0><<<dim3(DFF_/64, BL_/64), 256>>>((const float*)p_xn2, w_f1, b_f1,
                                                     nullptr, (float*)p_ffh, BL_, D_, DFF_);
    gemm_kernel<0,1><<<dim3(D_/64, BL_/64), 256>>>((const float*)p_ffh, w_f2, b_f2,
                                                   (const float*)p_x1, out, BL_, DFF_, D_);
    if(out_size >= BL_*D_ + 1){
        loss_kernel<<<1, 256>>>((const float*)p_spz, (const float*)p_ent, out + BL_*D_);
    }
}

// round 2
// speedup vs baseline: 1.5413x; 1.5413x over previous
#include <cuda_runtime.h>
#include <math.h>

#define B_   2
#define L_   1408
#define D_   512
#define H_   8
#define BH_  16
#define DFF_ 2048
#define BL_  (B_*L_)
#define KSEL_ 704

// ---------------- scratch ----------------
__device__ float g_xn[BL_*D_];
__device__ float g_q[BH_*L_*64];
__device__ float g_k[BH_*L_*64];
__device__ float g_adj[(size_t)BH_*L_*L_];
__device__ float g_xp[BL_*D_];
__device__ float g_gout[BL_*D_];
__device__ float g_x1[BL_*D_];
__device__ float g_xn2[BL_*D_];
__device__ float g_ffh[(size_t)BL_*DFF_];
__device__ float g_spz[L_*3];
__device__ float g_ent[1];

// ---------------- helpers ----------------
__device__ __forceinline__ float blk_sum(float v, float* s){
    int lane = threadIdx.x & 31, w = threadIdx.x >> 5;
    #pragma unroll
    for(int o=16;o;o>>=1) v += __shfl_down_sync(0xffffffffu, v, o);
    if(lane==0) s[w]=v;
    __syncthreads();
    int nw = blockDim.x >> 5;
    v = (threadIdx.x < nw) ? s[threadIdx.x] : 0.f;
    if(w==0){
        #pragma unroll
        for(int o=16;o;o>>=1) v += __shfl_down_sync(0xffffffffu, v, o);
        if(lane==0) s[0]=v;
    }
    __syncthreads();
    float r = s[0];
    __syncthreads();
    return r;
}

__device__ __forceinline__ float blk_max(float v, float* s){
    int lane = threadIdx.x & 31, w = threadIdx.x >> 5;
    #pragma unroll
    for(int o=16;o;o>>=1) v = fmaxf(v, __shfl_down_sync(0xffffffffu, v, o));
    if(lane==0) s[w]=v;
    __syncthreads();
    int nw = blockDim.x >> 5;
    v = (threadIdx.x < nw) ? s[threadIdx.x] : -INFINITY;
    if(w==0){
        #pragma unroll
        for(int o=16;o;o>>=1) v = fmaxf(v, __shfl_down_sync(0xffffffffu, v, o));
        if(lane==0) s[0]=v;
    }
    __syncthreads();
    float r = s[0];
    __syncthreads();
    return r;
}

__device__ __forceinline__ float geluf(float x){
    return 0.5f * x * (1.0f + erff(x * 0.7071067811865475f));
}

__device__ __forceinline__ unsigned tokey(float f){
    unsigned u = __float_as_uint(f);
    return (u & 0x80000000u) ? ~u : (u | 0x80000000u);
}

__device__ __forceinline__ unsigned f2tf(float x){
    unsigned r; asm("cvt.rna.tf32.f32 %0, %1;" : "=r"(r) : "f"(x)); return r;
}

__device__ __forceinline__ void mma_tf32(float c[4], unsigned a0, unsigned a1, unsigned a2, unsigned a3,
                                         unsigned b0, unsigned b1){
    asm volatile("mma.sync.aligned.m16n8k8.row.col.f32.tf32.tf32.f32 "
        "{%0,%1,%2,%3}, {%4,%5,%6,%7}, {%8,%9}, {%0,%1,%2,%3};"
        : "+f"(c[0]), "+f"(c[1]), "+f"(c[2]), "+f"(c[3])
        : "r"(a0), "r"(a1), "r"(a2), "r"(a3), "r"(b0), "r"(b1));
}

// ---------------- tf32 tensor-core GEMM ----------------
// C[m][n] = epi( sum_k A[m][k]*B[k][n] )
// BLAYOUT=1: Bsrc rows are [n][k] (ldb = stride between n-rows)
// BLAYOUT=0: Bsrc rows are [k][n] (ldb = stride between k-rows)
// N tile fixed at 64. BM in {128, 64}. 256 threads.
template<int BM, int BLAYOUT, int ACT, int RES, int BIAS>
__global__ void mma_gemm(const float* __restrict__ A, const float* __restrict__ Bsrc,
                         const float* __restrict__ bias, const float* __restrict__ res,
                         float* __restrict__ C,
                         int K, int lda, int ldb, int ldc,
                         int zdiv, size_t aB, size_t bOut, size_t bIn,
                         size_t cOut, size_t cIn)
{
    constexpr int WCOLS = (BM==128) ? 2 : 4;   // warps along N
    constexpr int NFRAG = 8/WCOLS;             // 8-wide n-frags per warp
    __shared__ unsigned As[BM][36];
    __shared__ unsigned Bs[(BLAYOUT==1) ? 64*36 : 32*68];

    int z = blockIdx.z;
    A    += (size_t)z * aB;
    Bsrc += (size_t)(z/zdiv)*bOut + (size_t)(z%zdiv)*bIn;
    const float* resp = RES ? (res + (size_t)(z/zdiv)*cOut + (size_t)(z%zdiv)*cIn) : nullptr;
    C    += (size_t)(z/zdiv)*cOut + (size_t)(z%zdiv)*cIn;

    int m0 = blockIdx.y*BM, n0 = blockIdx.x*64;
    int t = threadIdx.x, warp = t>>5, lane = t&31;
    int g = lane>>2, tg = lane&3;
    int wm = (warp/WCOLS)*32, wn = (warp%WCOLS)*(64/WCOLS);

    float acc[2][NFRAG][4] = {};

    for(int k0=0; k0<K; k0+=32){
        for(int i=t; i<BM*8; i+=256){
            int m = i>>3, k4 = (i&7)*4;
            float4 v = *(const float4*)(A + (size_t)(m0+m)*lda + k0 + k4);
            As[m][k4+0]=f2tf(v.x); As[m][k4+1]=f2tf(v.y);
            As[m][k4+2]=f2tf(v.z); As[m][k4+3]=f2tf(v.w);
        }
        if(BLAYOUT==1){
            for(int i=t; i<64*8; i+=256){
                int n = i>>3, k4 = (i&7)*4;
                float4 v = *(const float4*)(Bsrc + (size_t)(n0+n)*ldb + k0 + k4);
                unsigned* r = &Bs[n*36 + k4];
                r[0]=f2tf(v.x); r[1]=f2tf(v.y); r[2]=f2tf(v.z); r[3]=f2tf(v.w);
            }
        } else {
            for(int i=t; i<32*16; i+=256){
                int k = i>>4, n4 = (i&15)*4;
                float4 v = *(const float4*)(Bsrc + (size_t)(k0+k)*ldb + n0 + n4);
                unsigned* r = &Bs[k*68 + n4];
                r[0]=f2tf(v.x); r[1]=f2tf(v.y); r[2]=f2tf(v.z); r[3]=f2tf(v.w);
            }
        }
        __syncthreads();
        #pragma unroll
        for(int ks=0; ks<32; ks+=8){
            unsigned a[2][4];
            #pragma unroll
            for(int mi=0; mi<2; mi++){
                int r0 = wm + mi*16 + g;
                a[mi][0] = As[r0  ][ks+tg];
                a[mi][1] = As[r0+8][ks+tg];
                a[mi][2] = As[r0  ][ks+tg+4];
                a[mi][3] = As[r0+8][ks+tg+4];
            }
            #pragma unroll
            for(int nj=0; nj<NFRAG; nj++){
                int n = wn + nj*8 + g;
                unsigned b0, b1;
                if(BLAYOUT==1){ b0 = Bs[n*36 + ks+tg]; b1 = Bs[n*36 + ks+tg+4]; }
                else          { b0 = Bs[(ks+tg)*68 + n]; b1 = Bs[(ks+tg+4)*68 + n]; }
                #pragma unroll
                for(int mi=0; mi<2; mi++)
                    mma_tf32(acc[mi][nj], a[mi][0],a[mi][1],a[mi][2],a[mi][3], b0,b1);
            }
        }
        __syncthreads();
    }

    #pragma unroll
    for(int mi=0; mi<2; mi++){
        #pragma unroll
        for(int nj=0; nj<NFRAG; nj++){
            int col = n0 + wn + nj*8 + tg*2;
            #pragma unroll
            for(int half=0; half<2; half++){
                int m = m0 + wm + mi*16 + g + half*8;
                #pragma unroll
                for(int cc=0; cc<2; cc++){
                    float v = acc[mi][nj][half*2+cc];
                    int n = col + cc;
                    if(BIAS) v += bias[n];
                    if(ACT)  v = geluf(v);
                    if(RES)  v += resp[(size_t)m*ldc + n];
                    C[(size_t)m*ldc + n] = v;
                }
            }
        }
    }
}

// ---------------- small kernels ----------------
__global__ void zero_kernel(){
    int i = blockIdx.x*blockDim.x + threadIdx.x;
    if(i < L_*3) g_spz[i] = 0.f;
    if(i == 0)   g_ent[0] = 0.f;
}

__global__ void ln1_kernel(const float* __restrict__ x, const float* __restrict__ g,
                           const float* __restrict__ bta){
    __shared__ float s[32];
    int row = blockIdx.x;
    int t = threadIdx.x;
    const float* xr = x + (size_t)row*D_;
    float v0 = xr[t], v1 = xr[t+256];
    float mean = blk_sum(v0+v1, s) * (1.f/D_);
    float d0 = v0-mean, d1 = v1-mean;
    float var = blk_sum(d0*d0 + d1*d1, s) * (1.f/D_);
    float inv = rsqrtf(var + 1e-5f);
    float* o = g_xn + (size_t)row*D_;
    o[t]     = d0*inv*g[t]     + bta[t];
    o[t+256] = d1*inv*g[t+256] + bta[t+256];
}

__global__ void qk_kernel(const float* __restrict__ w1, const float* __restrict__ b1,
                          const float* __restrict__ w2, const float* __restrict__ b2){
    __shared__ float xr[512];
    __shared__ float W1[4096];
    __shared__ float W2[4096];
    int row = blockIdx.x;
    int t = threadIdx.x;
    xr[t] = g_xn[(size_t)row*D_ + t];
    for(int i=t;i<4096;i+=512){ W1[i]=w1[i]; W2[i]=w2[i]; }
    __syncthreads();
    int h = t >> 6, j = t & 63;
    const float* xv = xr + h*64;
    float a1 = b1[j], a2 = b2[j];
    #pragma unroll
    for(int d=0; d<64; d++){
        float v = xv[d];
        a1 += v * W1[d*64+j];
        a2 += v * W2[d*64+j];
    }
    int b = row / L_, l = row % L_;
    size_t o = (((size_t)b*H_ + h)*L_ + l)*64 + j;
    g_q[o] = a1; g_k[o] = a2;
}

// fused: top-k sparsify + MoE gating + loss stats + final mask mix + row softmax
__global__ void topk_gate_fin_kernel(const float* __restrict__ w_gate,
                                     const float* __restrict__ masks){
    __shared__ float srow[L_];
    __shared__ unsigned hist[256];
    __shared__ float rs[32];
    __shared__ unsigned sel[3];
    __shared__ float sgv[3];
    int row = blockIdx.x;         // bh*L + l
    int l = row % L_;
    int t = threadIdx.x;          // 256
    float* grow = g_adj + (size_t)row*L_;
    for(int i=t;i<L_;i+=256) srow[i] = grow[i];
    __syncthreads();

    // radix-select KSEL_-th smallest key
    unsigned prefix = 0, rank = KSEL_, ceq = 0;
    for(int p=3; p>=0; p--){
        hist[t] = 0;
        __syncthreads();
        unsigned shift = p*8;
        unsigned pm = (p==3) ? 0u : (0xFFFFFFFFu << (shift+8));
        for(int i=t;i<L_;i+=256){
            unsigned key = tokey(srow[i]);
            if((key & pm) == prefix) atomicAdd(&hist[(key>>shift)&255u], 1u);
        }
        __syncthreads();
        if(t==0){
            unsigned c = 0;
            for(unsigned bn=0; bn<256; bn++){
                unsigned hc = hist[bn];
                if(c + hc >= rank){ sel[0]=bn; sel[1]=c; sel[2]=hc; break; }
                c += hc;
            }
        }
        __syncthreads();
        prefix |= sel[0] << shift;
        rank   -= sel[1];
        ceq     = sel[2];
        __syncthreads();
    }
    unsigned KT = prefix;
    unsigned rzero = rank;

    for(int i=t;i<L_;i+=256){
        unsigned key = tokey(srow[i]);
        if(key < KT) srow[i] = 0.f;
        else if(key == KT){
            if(rzero >= ceq) srow[i] = 0.f;
            else{
                unsigned r = 0;
                for(int j=0;j<i;j++) if(tokey(grow[j]) == KT) r++;
                if(r < rzero) srow[i] = 0.f;
            }
        }
    }
    __syncthreads();

    // gate dot products from masked row
    float z0=0.f, z1=0.f, z2=0.f;
    for(int i=t;i<L_;i+=256){
        float v = srow[i];
        z0 += v * w_gate[i*3+0];
        z1 += v * w_gate[i*3+1];
        z2 += v * w_gate[i*3+2];
    }
    z0 = blk_sum(z0, rs); z1 = blk_sum(z1, rs); z2 = blk_sum(z2, rs);

    if(t==0){
        float mx = fmaxf(z0, fmaxf(z1, z2));
        float e0 = expf(z0-mx), e1 = expf(z1-mx), e2 = expf(z2-mx);
        float s = e0+e1+e2;
        float p[3] = { e0/s, e1/s, e2/s };
        atomicAdd(g_ent, p[0]*logf(p[0]+1e-10f) + p[1]*logf(p[1]+1e-10f) + p[2]*logf(p[2]+1e-10f));
        int o0=0, o1=1, o2=2;
        if(p[o1] > p[o0]){ int tt=o0; o0=o1; o1=tt; }
        if(p[o2] > p[o1]){ int tt=o1; o1=o2; o2=tt; }
        if(p[o1] > p[o0]){ int tt=o0; o0=o1; o1=tt; }
        float sp0=p[o0], sp1=p[o1], sp2=p[o2];
        bool m0f = sp0 > 0.5f, m1f = (sp0+sp1) > 0.5f, m2f = (sp0+sp1+sp2) > 0.5f;
        int j0 = m0f ? 0 : (m1f ? 1 : 2);
        bool k0 = (!m0f) || (j0==0);
        bool k1 = (!m1f) || (j0==1);
        bool k2 = (!m2f) || (j0==2);
        sgv[o0] = k0 ? 1.f : 0.f;
        sgv[o1] = k1 ? 1.f : 0.f;
        sgv[o2] = k2 ? 1.f : 0.f;
        if(k0) atomicAdd(&g_spz[l*3+0], sp0);
        if(k1) atomicAdd(&g_spz[l*3+1], sp1);
        if(k2) atomicAdd(&g_spz[l*3+2], sp2);
    }
    __syncthreads();

    // final mask mix + softmax, write final adj once
    float gv0 = sgv[0], gv1 = sgv[1], gv2 = sgv[2];
    const float* mk0 = masks + ((size_t)l*3 + 0)*L_;
    const float* mk1 = masks + ((size_t)l*3 + 1)*L_;
    const float* mk2 = masks + ((size_t)l*3 + 2)*L_;
    float mxv = -INFINITY;
    for(int i=t;i<L_;i+=256){
        float fm = (i==l) ? 1.f : 0.f;
        if(gv0 != 0.f) fm += mk0[i];
        if(gv1 != 0.f) fm += mk1[i];
        if(gv2 != 0.f) fm += mk2[i];
        float val = srow[i] * fm;
        srow[i] = val;
        mxv = fmaxf(mxv, val);
    }
    mxv = blk_max(mxv, rs);
    float ssum = 0.f;
    for(int i=t;i<L_;i+=256){
        float e = expf(srow[i] - mxv);
        srow[i] = e;
        ssum += e;
    }
    ssum = blk_sum(ssum, rs);
    float inv = 1.f / ssum;
    for(int i=t;i<L_;i+=256) grow[i] = srow[i] * inv;
}

__global__ void res_ln2_kernel(const float* __restrict__ x, const float* __restrict__ g,
                               const float* __restrict__ bta){
    __shared__ float s[32];
    int row = blockIdx.x;
    int t = threadIdx.x;
    const float* xr = x + (size_t)row*D_;
    const float* gr = g_gout + (size_t)row*D_;
    float a0 = xr[t]     + gr[t];
    float a1 = xr[t+256] + gr[t+256];
    float mean = blk_sum(a0+a1, s) * (1.f/D_);
    float d0 = a0-mean, d1 = a1-mean;
    float var = blk_sum(d0*d0 + d1*d1, s) * (1.f/D_);
    float inv = rsqrtf(var + 1e-5f);
    float* x1r  = g_x1  + (size_t)row*D_;
    float* xn2r = g_xn2 + (size_t)row*D_;
    x1r[t]      = a0;
    x1r[t+256]  = a1;
    xn2r[t]     = d0*inv*g[t]     + bta[t];
    xn2r[t+256] = d1*inv*g[t+256] + bta[t+256];
}

__global__ void loss_kernel(const float* __restrict__ spz, const float* __restrict__ ent,
                            float* __restrict__ out){
    __shared__ float rs[32];
    float s = 0.f, sq = 0.f;
    for(int i=threadIdx.x; i<L_*3; i+=256){
        float v = spz[i];
        s += v; sq += v*v;
    }
    s  = blk_sum(s, rs);
    sq = blk_sum(sq, rs);
    if(threadIdx.x == 0){
        const float n = (float)(L_*3);
        float mean = s / n;
        float var = (sq - n*mean*mean) / (n - 1.f);
        float loss_imp = var / (mean*mean + 1e-10f);
        float loss_dyn = -ent[0] / 48.f;
        out[0] = loss_imp + 0.1f*loss_dyn;
    }
}

// ---------------- launch ----------------
extern "C" void kernel_launch(void* const* d_in, const int* in_sizes, int n_in,
                              void* d_out, int out_size){
    const float* x      = (const float*)d_in[0];
    const float* masks  = (const float*)d_in[1];
    const float* ln1_g  = (const float*)d_in[2];
    const float* ln1_b  = (const float*)d_in[3];
    const float* w_p1   = (const float*)d_in[4];
    const float* b_p1   = (const float*)d_in[5];
    const float* w_p2   = (const float*)d_in[6];
    const float* b_p2   = (const float*)d_in[7];
    const float* w_gate = (const float*)d_in[8];
    const float* w_gcn  = (const float*)d_in[9];
    const float* b_gcn  = (const float*)d_in[10];
    const float* ln2_g  = (const float*)d_in[11];
    const float* ln2_b  = (const float*)d_in[12];
    const float* w_f1   = (const float*)d_in[13];
    const float* b_f1   = (const float*)d_in[14];
    const float* w_f2   = (const float*)d_in[15];
    const float* b_f2   = (const float*)d_in[16];
    float* out = (float*)d_out;

    void *p_q, *p_k, *p_adj, *p_xn, *p_xp, *p_gout, *p_x1, *p_xn2, *p_ffh, *p_spz, *p_ent;
    cudaGetSymbolAddress(&p_q,   g_q);
    cudaGetSymbolAddress(&p_k,   g_k);
    cudaGetSymbolAddress(&p_adj, g_adj);
    cudaGetSymbolAddress(&p_xn,  g_xn);
    cudaGetSymbolAddress(&p_xp,  g_xp);
    cudaGetSymbolAddress(&p_gout,g_gout);
    cudaGetSymbolAddress(&p_x1,  g_x1);
    cudaGetSymbolAddress(&p_xn2, g_xn2);
    cudaGetSymbolAddress(&p_ffh, g_ffh);
    cudaGetSymbolAddress(&p_spz, g_spz);
    cudaGetSymbolAddress(&p_ent, g_ent);

    zero_kernel<<<17, 256>>>();
    ln1_kernel<<<BL_, 256>>>(x, ln1_g, ln1_b);
    qk_kernel<<<BL_, 512>>>(w_p1, b_p1, w_p2, b_p2);

    // adj = gelu(Q K^T) per bh: M=N=1408, K=64
    mma_gemm<128,1,1,0,0><<<dim3(22,11,16), 256>>>(
        (const float*)p_q, (const float*)p_k, nullptr, nullptr, (float*)p_adj,
        64, 64, 64, L_,
        1, (size_t)L_*64, (size_t)L_*64, 0, (size_t)L_*(size_t)L_, 0);

    topk_gate_fin_kernel<<<BH_*L_, 256>>>(w_gate, masks);

    // xp = xn @ w_gcn + b_gcn: M=2816, K=512, N=512
    mma_gemm<64,0,0,0,1><<<dim3(8,44,1), 256>>>(
        (const float*)p_xn, w_gcn, b_gcn, nullptr, (float*)p_xp,
        512, 512, 512, 512,
        1, 0, 0, 0, 0, 0);

    // gout[b,i,h*64+d] = sum_j adj[bh,i,j] * xp[b,j,h*64+d]: per bh M=1408, K=1408, N=64
    mma_gemm<64,0,0,0,0><<<dim3(1,22,16), 256>>>(
        (const float*)p_adj, (const float*)p_xp, nullptr, nullptr, (float*)p_gout,
        L_, L_, D_, D_,
        H_, (size_t)L_*(size_t)L_, (size_t)L_*D_, 64, (size_t)L_*D_, 64);

    res_ln2_kernel<<<BL_, 256>>>(x, ln2_g, ln2_b);

    // ffh = gelu(xn2 @ w_f1 + b_f1): M=2816, K=512, N=2048
    mma_gemm<128,0,1,0,1><<<dim3(32,22,1), 256>>>(
        (const float*)p_xn2, w_f1, b_f1, nullptr, (float*)p_ffh,
        512, 512, DFF_, DFF_,
        1, 0, 0, 0, 0, 0);

    // out = ffh @ w_f2 + b_f2 + x1: M=2816, K=2048, N=512
    mma_gemm<64,0,0,1,1><<<dim3(8,44,1), 256>>>(
        (const float*)p_ffh, w_f2, b_f2, (const float*)p_x1, out,
        DFF_, DFF_, 512, 512,
        1, 0, 0, 0, 0, 0);

    if(out_size >= BL_*D_ + 1){
        loss_kernel<<<1, 256>>>((const float*)p_spz, (const float*)p_ent, out + BL_*D_);
    }
}

// round 5
// speedup vs baseline: 2.6723x; 1.7338x over previous
#include <cuda_runtime.h>
#include <math.h>

#define B_   2
#define L_   1408
#define D_   512
#define H_   8
#define BH_  16
#define DFF_ 2048
#define BL_  (B_*L_)
#define KSEL_ 704

// ---------------- scratch ----------------
__device__ float g_xn[BL_*D_];
__device__ float g_q[BH_*L_*64];
__device__ float g_k[BH_*L_*64];
__device__ float g_adj[(size_t)BH_*L_*L_];
__device__ float g_xp[BL_*D_];
__device__ float g_gout[4][BL_*D_];     // split-K partials
__device__ float g_x1[BL_*D_];
__device__ float g_xn2[BL_*D_];
__device__ float g_ffh[(size_t)BL_*DFF_];
__device__ float g_spz[L_*3];
__device__ float g_ent[1];

// ---------------- helpers ----------------
__device__ __forceinline__ float blk_sum(float v, float* s){
    int lane = threadIdx.x & 31, w = threadIdx.x >> 5;
    #pragma unroll
    for(int o=16;o;o>>=1) v += __shfl_down_sync(0xffffffffu, v, o);
    if(lane==0) s[w]=v;
    __syncthreads();
    int nw = blockDim.x >> 5;
    v = (threadIdx.x < nw) ? s[threadIdx.x] : 0.f;
    if(w==0){
        #pragma unroll
        for(int o=16;o;o>>=1) v += __shfl_down_sync(0xffffffffu, v, o);
        if(lane==0) s[0]=v;
    }
    __syncthreads();
    float r = s[0];
    __syncthreads();
    return r;
}

__device__ __forceinline__ float blk_max(float v, float* s){
    int lane = threadIdx.x & 31, w = threadIdx.x >> 5;
    #pragma unroll
    for(int o=16;o;o>>=1) v = fmaxf(v, __shfl_down_sync(0xffffffffu, v, o));
    if(lane==0) s[w]=v;
    __syncthreads();
    int nw = blockDim.x >> 5;
    v = (threadIdx.x < nw) ? s[threadIdx.x] : -INFINITY;
    if(w==0){
        #pragma unroll
        for(int o=16;o;o>>=1) v = fmaxf(v, __shfl_down_sync(0xffffffffu, v, o));
        if(lane==0) s[0]=v;
    }
    __syncthreads();
    float r = s[0];
    __syncthreads();
    return r;
}

__device__ __forceinline__ float geluf(float x){
    return 0.5f * x * (1.0f + erff(x * 0.7071067811865475f));
}

__device__ __forceinline__ unsigned tokey(float f){
    unsigned u = __float_as_uint(f);
    return (u & 0x80000000u) ? ~u : (u | 0x80000000u);
}

__device__ __forceinline__ void cpa16(void* s, const void* g){
    unsigned sa = (unsigned)__cvta_generic_to_shared(s);
    asm volatile("cp.async.cg.shared.global [%0], [%1], 16;" :: "r"(sa), "l"(g));
}
__device__ __forceinline__ void cp_commit(){ asm volatile("cp.async.commit_group;"); }
__device__ __forceinline__ void cp_wait0(){ asm volatile("cp.async.wait_group 0;"); }

__device__ __forceinline__ void mma_tf32(float c[4], unsigned a0, unsigned a1, unsigned a2, unsigned a3,
                                         unsigned b0, unsigned b1){
    asm volatile("mma.sync.aligned.m16n8k8.row.col.f32.tf32.tf32.f32 "
        "{%0,%1,%2,%3}, {%4,%5,%6,%7}, {%8,%9}, {%0,%1,%2,%3};"
        : "+f"(c[0]), "+f"(c[1]), "+f"(c[2]), "+f"(c[3])
        : "r"(a0), "r"(a1), "r"(a2), "r"(a3), "r"(b0), "r"(b1));
}

// ---------------- tf32 tensor-core GEMM, cp.async double-buffered, dynamic smem ----------------
// BLAYOUT=1: Bsrc rows are [n][k]; BLAYOUT=0: Bsrc rows are [k][n].
// N tile = 64. BM in {128,64}. 256 threads.
// SPLITK>1: blockIdx.x = split index (n0=0), K = per-split length, C += split*cSplit.
template<int BM, int BLAYOUT, int ACT, int RES, int BIAS, int SPLITK>
__global__ void __launch_bounds__(256)
mma_gemm(const float* __restrict__ A, const float* __restrict__ Bsrc,
         const float* __restrict__ bias, const float* __restrict__ res,
         float* __restrict__ C,
         int K, int lda, int ldb, int ldc,
         int zdiv, size_t aB, size_t bOut, size_t bIn,
         size_t cOut, size_t cIn, size_t cSplit)
{
    constexpr int WCOLS = (BM==128) ? 2 : 4;
    constexpr int NFRAG = 8/WCOLS;
    constexpr int ASZ = BM*36;
    constexpr int BSZ = (BLAYOUT==1) ? 64*36 : 32*68;
    extern __shared__ float smem[];
    float* As = smem;              // [2][ASZ]
    float* Bs = smem + 2*ASZ;      // [2][BSZ]

    int z = blockIdx.z;
    const float* Ap = A + (size_t)z*aB;
    const float* Bp = Bsrc + (size_t)(z/zdiv)*bOut + (size_t)(z%zdiv)*bIn;
    const float* resp = RES ? (res + (size_t)(z/zdiv)*cOut + (size_t)(z%zdiv)*cIn) : nullptr;
    float* Cp = C + (size_t)(z/zdiv)*cOut + (size_t)(z%zdiv)*cIn;

    int n0, kBase = 0;
    if(SPLITK > 1){ n0 = 0; kBase = blockIdx.x * K; Cp += (size_t)blockIdx.x * cSplit; }
    else n0 = blockIdx.x*64;
    int m0 = blockIdx.y*BM;
    int t = threadIdx.x, warp = t>>5, lane = t&31;
    int g = lane>>2, tg = lane&3;
    int wm = (warp/WCOLS)*32, wn = (warp%WCOLS)*(64/WCOLS);

    float acc[2][NFRAG][4] = {};

    auto load_tiles = [&](int buf, int k0){
        float* Ad = As + buf*ASZ;
        float* Bd = Bs + buf*BSZ;
        #pragma unroll
        for(int j=0; j<BM*8/256; j++){
            int i = t + j*256;
            int m = i>>3, k4 = (i&7)<<2;
            cpa16(&Ad[m*36+k4], Ap + (size_t)(m0+m)*lda + k0 + k4);
        }
        if(BLAYOUT==1){
            #pragma unroll
            for(int j=0; j<2; j++){
                int i = t + j*256;
                int n = i>>3, k4 = (i&7)<<2;
                cpa16(&Bd[n*36+k4], Bp + (size_t)(n0+n)*ldb + k0 + k4);
            }
        } else {
            #pragma unroll
            for(int j=0; j<2; j++){
                int i = t + j*256;
                int k = i>>4, n4 = (i&15)<<2;
                cpa16(&Bd[k*68+n4], Bp + (size_t)(k0+k)*ldb + n0 + n4);
            }
        }
        cp_commit();
    };

    int nIter = K/32;
    load_tiles(0, kBase);
    for(int it=0; it<nIter; it++){
        cp_wait0();
        __syncthreads();
        if(it+1 < nIter) load_tiles((it+1)&1, kBase + (it+1)*32);
        int buf = it&1;
        const float* Ab = As + buf*ASZ;
        const float* Bb = Bs + buf*BSZ;
        #pragma unroll
        for(int ks=0; ks<32; ks+=8){
            unsigned a[2][4];
            #pragma unroll
            for(int mi=0; mi<2; mi++){
                int r0 = wm + mi*16 + g;
                a[mi][0] = __float_as_uint(Ab[r0*36     + ks+tg]);
                a[mi][1] = __float_as_uint(Ab[(r0+8)*36 + ks+tg]);
                a[mi][2] = __float_as_uint(Ab[r0*36     + ks+tg+4]);
                a[mi][3] = __float_as_uint(Ab[(r0+8)*36 + ks+tg+4]);
            }
            #pragma unroll
            for(int nj=0; nj<NFRAG; nj++){
                int n = wn + nj*8 + g;
                unsigned b0, b1;
                if(BLAYOUT==1){ b0 = __float_as_uint(Bb[n*36 + ks+tg]);
                                b1 = __float_as_uint(Bb[n*36 + ks+tg+4]); }
                else          { b0 = __float_as_uint(Bb[(ks+tg)*68 + n]);
                                b1 = __float_as_uint(Bb[(ks+tg+4)*68 + n]); }
                #pragma unroll
                for(int mi=0; mi<2; mi++)
                    mma_tf32(acc[mi][nj], a[mi][0],a[mi][1],a[mi][2],a[mi][3], b0,b1);
            }
        }
        __syncthreads();
    }

    #pragma unroll
    for(int mi=0; mi<2; mi++){
        #pragma unroll
        for(int nj=0; nj<NFRAG; nj++){
            int col = n0 + wn + nj*8 + tg*2;
            #pragma unroll
            for(int half=0; half<2; half++){
                int m = m0 + wm + mi*16 + g + half*8;
                float v0 = acc[mi][nj][half*2+0];
                float v1 = acc[mi][nj][half*2+1];
                if(BIAS){ v0 += bias[col]; v1 += bias[col+1]; }
                if(ACT){ v0 = geluf(v0); v1 = geluf(v1); }
                if(RES){
                    v0 += resp[(size_t)m*ldc + col];
                    v1 += resp[(size_t)m*ldc + col+1];
                }
                *(float2*)(Cp + (size_t)m*ldc + col) = make_float2(v0, v1);
            }
        }
    }
}

template<int BM, int BLAYOUT>
constexpr int gemm_smem(){
    return (2*BM*36 + 2*((BLAYOUT==1) ? 64*36 : 32*68)) * 4;
}

// ---------------- small kernels ----------------
__global__ void zero_kernel(){
    int i = blockIdx.x*blockDim.x + threadIdx.x;
    if(i < L_*3) g_spz[i] = 0.f;
    if(i == 0)   g_ent[0] = 0.f;
}

__global__ void ln1_kernel(const float* __restrict__ x, const float* __restrict__ g,
                           const float* __restrict__ bta){
    __shared__ float s[32];
    int row = blockIdx.x;
    int t = threadIdx.x;
    const float* xr = x + (size_t)row*D_;
    float v0 = xr[t], v1 = xr[t+256];
    float mean = blk_sum(v0+v1, s) * (1.f/D_);
    float d0 = v0-mean, d1 = v1-mean;
    float var = blk_sum(d0*d0 + d1*d1, s) * (1.f/D_);
    float inv = rsqrtf(var + 1e-5f);
    float* o = g_xn + (size_t)row*D_;
    o[t]     = d0*inv*g[t]     + bta[t];
    o[t+256] = d1*inv*g[t+256] + bta[t+256];
}

__global__ void qk_kernel(const float* __restrict__ w1, const float* __restrict__ b1,
                          const float* __restrict__ w2, const float* __restrict__ b2){
    __shared__ float xr[512];
    __shared__ float W1[4096];
    __shared__ float W2[4096];
    int row = blockIdx.x;
    int t = threadIdx.x;
    xr[t] = g_xn[(size_t)row*D_ + t];
    for(int i=t;i<4096;i+=512){ W1[i]=w1[i]; W2[i]=w2[i]; }
    __syncthreads();
    int h = t >> 6, j = t & 63;
    const float* xv = xr + h*64;
    float a1 = b1[j], a2 = b2[j];
    #pragma unroll
    for(int d=0; d<64; d++){
        float v = xv[d];
        a1 += v * W1[d*64+j];
        a2 += v * W2[d*64+j];
    }
    int b = row / L_, l = row % L_;
    size_t o = (((size_t)b*H_ + h)*L_ + l)*64 + j;
    g_q[o] = a1; g_k[o] = a2;
}

// fused: top-k sparsify + MoE gating + loss stats + final mask mix + row softmax
__global__ void topk_gate_fin_kernel(const float* __restrict__ w_gate,
                                     const float* __restrict__ masks){
    __shared__ float srow[L_];
    __shared__ unsigned hist[256];
    __shared__ unsigned wsum[8];
    __shared__ float rs[32];
    __shared__ unsigned sel[3];
    __shared__ unsigned skt;
    __shared__ float sgv[3];
    int row = blockIdx.x;         // bh*L + l
    int l = row % L_;
    int t = threadIdx.x;          // 256
    int lane = t & 31, w = t >> 5;
    float* grow = g_adj + (size_t)row*L_;
    for(int i=t; i<L_/4; i+=256)
        *(float4*)(srow + i*4) = *(const float4*)(grow + i*4);
    __syncthreads();

    // radix-select KSEL_-th smallest key (MSB-first, 8 bits/pass)
    unsigned prefix = 0, rank = KSEL_, ceq = 0;
    int pdone = -1;
    for(int p=3; p>=0; p--){
        hist[t] = 0;
        __syncthreads();
        unsigned shift = p*8;
        unsigned pm = (p==3) ? 0u : (0xFFFFFFFFu << (shift+8));
        for(int i=t;i<L_;i+=256){
            unsigned key = tokey(srow[i]);
            if((key & pm) == prefix) atomicAdd(&hist[(key>>shift)&255u], 1u);
        }
        __syncthreads();
        // parallel inclusive scan over 256 bins
        unsigned h = hist[t], v = h;
        #pragma unroll
        for(int o=1;o<32;o<<=1){
            unsigned nv = __shfl_up_sync(0xffffffffu, v, o);
            if(lane >= o) v += nv;
        }
        if(lane==31) wsum[w] = v;
        __syncthreads();
        unsigned wp = 0;
        #pragma unroll
        for(int i=0;i<8;i++) if(i<w) wp += wsum[i];
        unsigned incl = v + wp, excl = incl - h;
        if(incl >= rank && excl < rank){ sel[0]=(unsigned)t; sel[1]=excl; sel[2]=h; }
        __syncthreads();
        prefix |= sel[0] << shift;
        rank   -= sel[1];
        ceq     = sel[2];
        __syncthreads();
        if(ceq == 1 && p > 0){ pdone = p; break; }
    }
    unsigned KT;
    if(pdone > 0){
        unsigned pm2 = 0xFFFFFFFFu << (pdone*8);
        for(int i=t;i<L_;i+=256){
            unsigned key = tokey(srow[i]);
            if((key & pm2) == prefix) skt = key;
        }
        __syncthreads();
        KT = skt; rank = 1; ceq = 1;
    } else {
        KT = prefix;
    }
    unsigned rzero = rank;

    for(int i=t;i<L_;i+=256){
        unsigned key = tokey(srow[i]);
        if(key < KT) srow[i] = 0.f;
        else if(key == KT){
            if(rzero >= ceq) srow[i] = 0.f;
            else{
                unsigned r = 0;
                for(int j=0;j<i;j++) if(tokey(grow[j]) == KT) r++;
                if(r < rzero) srow[i] = 0.f;
            }
        }
    }
    __syncthreads();

    // gate dot products from masked row
    float z0=0.f, z1=0.f, z2=0.f;
    for(int i=t;i<L_;i+=256){
        float v = srow[i];
        z0 += v * w_gate[i*3+0];
        z1 += v * w_gate[i*3+1];
        z2 += v * w_gate[i*3+2];
    }
    z0 = blk_sum(z0, rs); z1 = blk_sum(z1, rs); z2 = blk_sum(z2, rs);

    if(t==0){
        float mx = fmaxf(z0, fmaxf(z1, z2));
        float e0 = expf(z0-mx), e1 = expf(z1-mx), e2 = expf(z2-mx);
        float s = e0+e1+e2;
        float p[3] = { e0/s, e1/s, e2/s };
        atomicAdd(g_ent, p[0]*logf(p[0]+1e-10f) + p[1]*logf(p[1]+1e-10f) + p[2]*logf(p[2]+1e-10f));
        int o0=0, o1=1, o2=2;
        if(p[o1] > p[o0]){ int tt=o0; o0=o1; o1=tt; }
        if(p[o2] > p[o1]){ int tt=o1; o1=o2; o2=tt; }
        if(p[o1] > p[o0]){ int tt=o0; o0=o1; o1=tt; }
        float sp0=p[o0], sp1=p[o1], sp2=p[o2];
        bool m0f = sp0 > 0.5f, m1f = (sp0+sp1) > 0.5f, m2f = (sp0+sp1+sp2) > 0.5f;
        int j0 = m0f ? 0 : (m1f ? 1 : 2);
        bool k0 = (!m0f) || (j0==0);
        bool k1 = (!m1f) || (j0==1);
        bool k2 = (!m2f) || (j0==2);
        sgv[o0] = k0 ? 1.f : 0.f;
        sgv[o1] = k1 ? 1.f : 0.f;
        sgv[o2] = k2 ? 1.f : 0.f;
        if(k0) atomicAdd(&g_spz[l*3+0], sp0);
        if(k1) atomicAdd(&g_spz[l*3+1], sp1);
        if(k2) atomicAdd(&g_spz[l*3+2], sp2);
    }
    __syncthreads();

    // final mask mix + softmax, write final adj once
    float gv0 = sgv[0], gv1 = sgv[1], gv2 = sgv[2];
    const float* mk0 = masks + ((size_t)l*3 + 0)*L_;
    const float* mk1 = masks + ((size_t)l*3 + 1)*L_;
    const float* mk2 = masks + ((size_t)l*3 + 2)*L_;
    float mxv = -INFINITY;
    for(int i=t;i<L_;i+=256){
        float fm = (i==l) ? 1.f : 0.f;
        if(gv0 != 0.f) fm += mk0[i];
        if(gv1 != 0.f) fm += mk1[i];
        if(gv2 != 0.f) fm += mk2[i];
        float val = srow[i] * fm;
        srow[i] = val;
        mxv = fmaxf(mxv, val);
    }
    mxv = blk_max(mxv, rs);
    float ssum = 0.f;
    for(int i=t;i<L_;i+=256){
        float e = expf(srow[i] - mxv);
        srow[i] = e;
        ssum += e;
    }
    ssum = blk_sum(ssum, rs);
    float inv = 1.f / ssum;
    for(int i=t; i<L_/4; i+=256){
        float4 v = *(float4*)(srow + i*4);
        v.x *= inv; v.y *= inv; v.z *= inv; v.w *= inv;
        *(float4*)(grow + i*4) = v;
    }
}

__global__ void res_ln2_kernel(const float* __restrict__ x, const float* __restrict__ g,
                               const float* __restrict__ bta){
    __shared__ float s[32];
    int row = blockIdx.x;
    int t = threadIdx.x;
    const float* xr = x + (size_t)row*D_;
    float a0 = xr[t], a1 = xr[t+256];
    #pragma unroll
    for(int sp=0; sp<4; sp++){
        a0 += g_gout[sp][(size_t)row*D_ + t];
        a1 += g_gout[sp][(size_t)row*D_ + t + 256];
    }
    float mean = blk_sum(a0+a1, s) * (1.f/D_);
    float d0 = a0-mean, d1 = a1-mean;
    float var = blk_sum(d0*d0 + d1*d1, s) * (1.f/D_);
    float inv = rsqrtf(var + 1e-5f);
    float* x1r  = g_x1  + (size_t)row*D_;
    float* xn2r = g_xn2 + (size_t)row*D_;
    x1r[t]      = a0;
    x1r[t+256]  = a1;
    xn2r[t]     = d0*inv*g[t]     + bta[t];
    xn2r[t+256] = d1*inv*g[t+256] + bta[t+256];
}

__global__ void loss_kernel(const float* __restrict__ spz, const float* __restrict__ ent,
                            float* __restrict__ out){
    __shared__ float rs[32];
    float s = 0.f, sq = 0.f;
    for(int i=threadIdx.x; i<L_*3; i+=256){
        float v = spz[i];
        s += v; sq += v*v;
    }
    s  = blk_sum(s, rs);
    sq = blk_sum(sq, rs);
    if(threadIdx.x == 0){
        const float n = (float)(L_*3);
        float mean = s / n;
        float var = (sq - n*mean*mean) / (n - 1.f);
        float loss_imp = var / (mean*mean + 1e-10f);
        float loss_dyn = -ent[0] / 48.f;
        out[0] = loss_imp + 0.1f*loss_dyn;
    }
}

// ---------------- launch ----------------
extern "C" void kernel_launch(void* const* d_in, const int* in_sizes, int n_in,
                              void* d_out, int out_size){
    const float* x      = (const float*)d_in[0];
    const float* masks  = (const float*)d_in[1];
    const float* ln1_g  = (const float*)d_in[2];
    const float* ln1_b  = (const float*)d_in[3];
    const float* w_p1   = (const float*)d_in[4];
    const float* b_p1   = (const float*)d_in[5];
    const float* w_p2   = (const float*)d_in[6];
    const float* b_p2   = (const float*)d_in[7];
    const float* w_gate = (const float*)d_in[8];
    const float* w_gcn  = (const float*)d_in[9];
    const float* b_gcn  = (const float*)d_in[10];
    const float* ln2_g  = (const float*)d_in[11];
    const float* ln2_b  = (const float*)d_in[12];
    const float* w_f1   = (const float*)d_in[13];
    const float* b_f1   = (const float*)d_in[14];
    const float* w_f2   = (const float*)d_in[15];
    const float* b_f2   = (const float*)d_in[16];
    float* out = (float*)d_out;

    void *p_q, *p_k, *p_adj, *p_xn, *p_xp, *p_gout, *p_x1, *p_xn2, *p_ffh, *p_spz, *p_ent;
    cudaGetSymbolAddress(&p_q,   g_q);
    cudaGetSymbolAddress(&p_k,   g_k);
    cudaGetSymbolAddress(&p_adj, g_adj);
    cudaGetSymbolAddress(&p_xn,  g_xn);
    cudaGetSymbolAddress(&p_xp,  g_xp);
    cudaGetSymbolAddress(&p_gout,g_gout);
    cudaGetSymbolAddress(&p_x1,  g_x1);
    cudaGetSymbolAddress(&p_xn2, g_xn2);
    cudaGetSymbolAddress(&p_ffh, g_ffh);
    cudaGetSymbolAddress(&p_spz, g_spz);
    cudaGetSymbolAddress(&p_ent, g_ent);

    // raise dynamic smem limits (host attribute calls; graph-capture safe)
    cudaFuncSetAttribute(mma_gemm<128,1,1,0,0,1>, cudaFuncAttributeMaxDynamicSharedMemorySize, gemm_smem<128,1>());
    cudaFuncSetAttribute(mma_gemm<64,0,0,0,1,1>,  cudaFuncAttributeMaxDynamicSharedMemorySize, gemm_smem<64,0>());
    cudaFuncSetAttribute(mma_gemm<128,0,0,0,0,4>, cudaFuncAttributeMaxDynamicSharedMemorySize, gemm_smem<128,0>());
    cudaFuncSetAttribute(mma_gemm<128,0,1,0,1,1>, cudaFuncAttributeMaxDynamicSharedMemorySize, gemm_smem<128,0>());
    cudaFuncSetAttribute(mma_gemm<64,0,0,1,1,1>,  cudaFuncAttributeMaxDynamicSharedMemorySize, gemm_smem<64,0>());

    zero_kernel<<<17, 256>>>();
    ln1_kernel<<<BL_, 256>>>(x, ln1_g, ln1_b);
    qk_kernel<<<BL_, 512>>>(w_p1, b_p1, w_p2, b_p2);

    // adj = gelu(Q K^T) per bh: M=N=1408, K=64
    mma_gemm<128,1,1,0,0,1><<<dim3(22,11,16), 256, gemm_smem<128,1>()>>>(
        (const float*)p_q, (const float*)p_k, nullptr, nullptr, (float*)p_adj,
        64, 64, 64, L_,
        1, (size_t)L_*64, (size_t)L_*64, 0, (size_t)L_*(size_t)L_, 0, 0);

    topk_gate_fin_kernel<<<BH_*L_, 256>>>(w_gate, masks);

    // xp = xn @ w_gcn + b_gcn: M=2816, K=512, N=512
    mma_gemm<64,0,0,0,1,1><<<dim3(8,44,1), 256, gemm_smem<64,0>()>>>(
        (const float*)p_xn, w_gcn, b_gcn, nullptr, (float*)p_xp,
        512, 512, 512, 512,
        1, 0, 0, 0, 0, 0, 0);

    // gout partials: per bh M=1408, N=64, K=1408, split-K=4 (352 each)
    mma_gemm<128,0,0,0,0,4><<<dim3(4,11,16), 256, gemm_smem<128,0>()>>>(
        (const float*)p_adj, (const float*)p_xp, nullptr, nullptr, (float*)p_gout,
        352, L_, D_, D_,
        H_, (size_t)L_*(size_t)L_, (size_t)L_*D_, 64, (size_t)L_*D_, 64, (size_t)BL_*D_);

    res_ln2_kernel<<<BL_, 256>>>(x, ln2_g, ln2_b);

    // ffh = gelu(xn2 @ w_f1 + b_f1): M=2816, K=512, N=2048
    mma_gemm<128,0,1,0,1,1><<<dim3(32,22,1), 256, gemm_smem<128,0>()>>>(
        (const float*)p_xn2, w_f1, b_f1, nullptr, (float*)p_ffh,
        512, 512, DFF_, DFF_,
        1, 0, 0, 0, 0, 0, 0);

    // out = ffh @ w_f2 + b_f2 + x1: M=2816, K=2048, N=512
    mma_gemm<64,0,0,1,1,1><<<dim3(8,44,1), 256, gemm_smem<64,0>()>>>(
        (const float*)p_ffh, w_f2, b_f2, (const float*)p_x1, out,
        DFF_, DFF_, 512, 512,
        1, 0, 0, 0, 0, 0, 0);

    if(out_size >= BL_*D_ + 1){
        loss_kernel<<<1, 256>>>((const float*)p_spz, (const float*)p_ent, out + BL_*D_);
    }
}